// round 4
// baseline (speedup 1.0000x reference)
#include <cuda_runtime.h>

// Problem constants
#define BATCH 4
#define T 32
#define NTOK (BATCH * T)      // 128
#define C 512
#define ENC 32
#define DIM 1024

// Scratch (no allocations allowed): device globals
__device__ float2 d_M[4][32][32];   // a-side matrices (P_k = M_k * enc_i)
__device__ float2 d_N[4][32][32];   // b-side matrices (Q_k = N_k * enc_j)
__device__ float2 d_P[NTOK][4][32];
__device__ float2 d_Q[NTOK][4][32];

__device__ __forceinline__ float2 cmul(float2 a, float2 b) {
    return make_float2(a.x * b.x - a.y * b.y, a.x * b.y + a.y * b.x);
}

// ---------------------------------------------------------------------------
// Kernel 1: build the 8 32x32 complex matrices from the thetas.
//   Ga  = kron_{j=0..4}(RY0_j * RX0_j)   (wire j -> bit (4-j) of a-index)
//   Gb  = kron_{j=5..9}(RY0_j * RX0_j)
//   G2a = kron_{j=0..4}(RY1_j)  (real), G2b similar
//   CNOT prefix-chain inverse permutation: sigma_inv(m) = m ^ (m >> 1)
//   Rank-4 split over the two cross CNOTs (4,5) and (9,0):
//   M_k[r,c] = sum_{m: m&1==p} G2a[r][m ^ (q<<4)] * Ga[m ^ (m>>1)][c]
//   N_k[r,c] = sum_{m: m&1==q} G2b[r][m] * Gb[(m ^ (m>>1)) ^ (p<<4)][c]
//   with p = k>>1, q = k&1.
// Block = 256 threads; each thread handles 4 (r,c) cells.
// ---------------------------------------------------------------------------
__global__ void __launch_bounds__(256)
build_mats_kernel(const float* __restrict__ th_rx0,
                  const float* __restrict__ th_ry0,
                  const float* __restrict__ th_ry1) {
    __shared__ float2 M1w[10][2][2];  // layer-1 combined RY*RX per wire
    __shared__ float  M2w[10][2][2];  // layer-2 RY per wire (real)
    __shared__ float2 Ga[32][32], Gb[32][32];
    __shared__ float  G2a[32][32], G2b[32][32];

    int tid = threadIdx.x;  // 256
    if (tid < 10) {
        float crx = cosf(th_rx0[tid] * 0.5f), srx = sinf(th_rx0[tid] * 0.5f);
        float cry = cosf(th_ry0[tid] * 0.5f), sry = sinf(th_ry0[tid] * 0.5f);
        // M = RY * RX
        M1w[tid][0][0] = make_float2( cry * crx,  sry * srx);
        M1w[tid][0][1] = make_float2(-sry * crx, -cry * srx);
        M1w[tid][1][0] = make_float2( sry * crx, -cry * srx);
        M1w[tid][1][1] = make_float2( cry * crx, -sry * srx);
        float c1 = cosf(th_ry1[tid] * 0.5f), s1 = sinf(th_ry1[tid] * 0.5f);
        M2w[tid][0][0] =  c1; M2w[tid][0][1] = -s1;
        M2w[tid][1][0] =  s1; M2w[tid][1][1] =  c1;
    }
    __syncthreads();

    // Each thread fills 4 cells: rows {chunk*8 ...}, 256 threads cover 8 rows/pass
    for (int cell = tid; cell < 1024; cell += 256) {
        int r = cell >> 5, c = cell & 31;
        float2 ga = make_float2(1.f, 0.f), gb = make_float2(1.f, 0.f);
        float g2a = 1.f, g2b = 1.f;
#pragma unroll
        for (int j = 0; j < 5; j++) {
            int rb = (r >> (4 - j)) & 1;
            int cb = (c >> (4 - j)) & 1;
            ga  = cmul(ga, M1w[j][rb][cb]);
            gb  = cmul(gb, M1w[5 + j][rb][cb]);
            g2a *= M2w[j][rb][cb];
            g2b *= M2w[5 + j][rb][cb];
        }
        Ga[r][c] = ga; Gb[r][c] = gb; G2a[r][c] = g2a; G2b[r][c] = g2b;
    }
    __syncthreads();

    for (int cell = tid; cell < 1024; cell += 256) {
        int r = cell >> 5, c = cell & 31;
        for (int k = 0; k < 4; k++) {
            int pa = k >> 1;            // a-projector parity (p)
            int fa = (k & 1) << 4;      // X-flip on a-MSB (q)
            int pb = k & 1;             // b-projector parity (q)
            int xb = (k >> 1) << 4;     // X-flip on b-MSB before Cb (p)

            float2 accM = make_float2(0.f, 0.f);
            float2 accN = make_float2(0.f, 0.f);
            for (int mm = 0; mm < 16; mm++) {
                int m = (mm << 1) | pa;
                int si = m ^ (m >> 1);
                float2 t = Ga[si][c];
                float g = G2a[r][m ^ fa];
                accM.x += g * t.x; accM.y += g * t.y;

                int m2 = (mm << 1) | pb;
                int si2 = (m2 ^ (m2 >> 1)) ^ xb;
                float2 t2 = Gb[si2][c];
                float g2 = G2b[r][m2];
                accN.x += g2 * t2.x; accN.y += g2 * t2.y;
            }
            d_M[k][r][c] = accM;
            d_N[k][r][c] = accN;
        }
    }
}

// ---------------------------------------------------------------------------
// Kernel 2: per token: enc = normalize(x @ W^T + b), then
//           P_k = M_k * enc, Q_k = N_k * enc   (complex matrix * real vector)
// grid = 128 (one block per token), block = 128 threads.
// ---------------------------------------------------------------------------
__global__ void __launch_bounds__(128)
enc_pq_kernel(const float* __restrict__ x,
              const float* __restrict__ W,
              const float* __restrict__ bias) {
    int tok = blockIdx.x;
    const float* xr = x + (size_t)tok * C;

    __shared__ float partial[4][32];
    __shared__ float e[32];

    int tid = threadIdx.x;          // 128
    int k = tid & 31, p = tid >> 5; // output idx, c-chunk
    const float* wr = W + (size_t)k * C + p * 128;
    const float* xc = xr + p * 128;
    float s = 0.f;
#pragma unroll 8
    for (int cc = 0; cc < 128; cc++) s += xc[cc] * wr[cc];
    partial[p][k] = s;
    __syncthreads();

    if (tid < 32) {
        float v = partial[0][tid] + partial[1][tid] + partial[2][tid] +
                  partial[3][tid] + bias[tid];
        float sq = v * v;
#pragma unroll
        for (int o = 16; o; o >>= 1) sq += __shfl_xor_sync(0xffffffffu, sq, o);
        e[tid] = v * rsqrtf(sq);
    }
    __syncthreads();

    // 256 complex outputs (4 P-vectors + 4 Q-vectors of 32), 2 per thread
#pragma unroll
    for (int pass = 0; pass < 2; pass++) {
        int o = tid + pass * 128;
        int which = o >> 7;             // 0 -> P, 1 -> Q
        int k4 = (o >> 5) & 3;
        int rr = o & 31;
        const float2* Mrow = which ? &d_N[k4][rr][0] : &d_M[k4][rr][0];
        float re = 0.f, im = 0.f;
#pragma unroll
        for (int c2 = 0; c2 < 32; c2++) {
            float ev = e[c2];
            float2 m = Mrow[c2];
            re += m.x * ev;
            im += m.y * ev;
        }
        if (which) d_Q[tok][k4][rr] = make_float2(re, im);
        else       d_P[tok][k4][rr] = make_float2(re, im);
    }
}

// ---------------------------------------------------------------------------
// Kernel 3a: rank-4 expansion, interleaved complex64 output (re,im pairs).
// out[b, i*T+j, a*32 + bi] = sum_k P_k(b,i)[a] * Q_k(b,j)[bi]
// grid = 4096 blocks, block = 512; each thread writes 2 complex = 1 float4.
// nf4_limit clamps total float4 stores (never exceed the real buffer).
// ---------------------------------------------------------------------------
__global__ void __launch_bounds__(512)
expand_cplx_kernel(float4* __restrict__ out, long long nf4_limit) {
    int blk = blockIdx.x;          // b*1024 + i*32 + j
    int b = blk >> 10;
    int i = (blk >> 5) & 31;
    int j = blk & 31;

    __shared__ float2 Ps[4][32];
    __shared__ float2 Qs[4][32];

    int tid = threadIdx.x;  // 512
    if (tid < 128) {
        Ps[tid >> 5][tid & 31] = d_P[b * T + i][tid >> 5][tid & 31];
    } else if (tid < 256) {
        int t = tid - 128;
        Qs[t >> 5][t & 31] = d_Q[b * T + j][t >> 5][t & 31];
    }
    __syncthreads();

    int e0 = tid * 2;
    int a  = e0 >> 5;
    int b0 = e0 & 31;

    float re0 = 0.f, im0 = 0.f, re1 = 0.f, im1 = 0.f;
#pragma unroll
    for (int k = 0; k < 4; k++) {
        float2 P  = Ps[k][a];
        float2 Q0 = Qs[k][b0];
        float2 Q1 = Qs[k][b0 + 1];
        re0 += P.x * Q0.x - P.y * Q0.y;
        im0 += P.x * Q0.y + P.y * Q0.x;
        re1 += P.x * Q1.x - P.y * Q1.y;
        im1 += P.x * Q1.y + P.y * Q1.x;
    }
    long long idx = (long long)blk * 512 + tid;
    if (idx < nf4_limit)
        out[idx] = make_float4(re0, im0, re1, im1);
}

// ---------------------------------------------------------------------------
// Kernel 3b: rank-4 expansion, REAL-part-only float32 output (4M floats).
// Each thread writes 2 reals = 1 float2. Total 16MB.
// ---------------------------------------------------------------------------
__global__ void __launch_bounds__(512)
expand_real_kernel(float2* __restrict__ out) {
    int blk = blockIdx.x;
    int b = blk >> 10;
    int i = (blk >> 5) & 31;
    int j = blk & 31;

    __shared__ float2 Ps[4][32];
    __shared__ float2 Qs[4][32];

    int tid = threadIdx.x;  // 512
    if (tid < 128) {
        Ps[tid >> 5][tid & 31] = d_P[b * T + i][tid >> 5][tid & 31];
    } else if (tid < 256) {
        int t = tid - 128;
        Qs[t >> 5][t & 31] = d_Q[b * T + j][t >> 5][t & 31];
    }
    __syncthreads();

    int e0 = tid * 2;
    int a  = e0 >> 5;
    int b0 = e0 & 31;

    float re0 = 0.f, re1 = 0.f;
#pragma unroll
    for (int k = 0; k < 4; k++) {
        float2 P  = Ps[k][a];
        float2 Q0 = Qs[k][b0];
        float2 Q1 = Qs[k][b0 + 1];
        re0 += P.x * Q0.x - P.y * Q0.y;
        re1 += P.x * Q1.x - P.y * Q1.y;
    }
    out[(long long)blk * 512 + tid] = make_float2(re0, re1);
}

// ---------------------------------------------------------------------------
extern "C" void kernel_launch(void* const* d_in, const int* in_sizes, int n_in,
                              void* d_out, int out_size) {
    // Resolve inputs by element count (order-independent):
    //   x: 65536 (B*T*C), W_tok: 16384 (ENC*C), b_tok: 32 (ENC),
    //   thetas: three size-10 arrays, relative order rx0, ry0, ry1.
    const float* x = nullptr;
    const float* W = nullptr;
    const float* bvec = nullptr;
    const float* th[3] = {nullptr, nullptr, nullptr};
    int nth = 0;
    for (int i = 0; i < n_in; i++) {
        int sz = in_sizes[i];
        const float* p = (const float*)d_in[i];
        if (sz == BATCH * T * C)      x = p;
        else if (sz == ENC * C)       W = p;
        else if (sz == ENC)           bvec = p;
        else if (sz == 10 && nth < 3) th[nth++] = p;
    }
    if (!x || !W || !bvec || nth != 3) return;

    build_mats_kernel<<<1, 256>>>(th[0], th[1], th[2]);
    enc_pq_kernel<<<NTOK, 128>>>(x, W, bvec);

    if (out_size == 4194304) {
        // float32 output, 4M elements (16MB): real parts only.
        expand_real_kernel<<<BATCH * T * T, 512>>>((float2*)d_out);
    } else {
        // Interleaved (re,im) float pairs: 8M floats = 2M float4 (32MB).
        // Clamp stores so we never exceed the buffer implied by out_size.
        long long nfloats = (long long)out_size;
        if (nfloats > 8388608LL) nfloats = 8388608LL;
        long long nf4 = nfloats / 4;
        if (nf4 > 2097152LL) nf4 = 2097152LL;
        expand_cplx_kernel<<<BATCH * T * T, 512>>>((float4*)d_out, nf4);
    }
}

// round 6
// speedup vs baseline: 1.5838x; 1.5838x over previous
#include <cuda_runtime.h>

// Problem constants
#define BATCH 4
#define T 32
#define NTOK (BATCH * T)      // 128
#define C 512
#define ENC 32
#define DIM 1024

// Scratch (no allocations allowed): device globals
__device__ float2 d_P[NTOK][4][32];
__device__ float2 d_Q[NTOK][4][32];

__device__ __forceinline__ float2 cmul(float2 a, float2 b) {
    return make_float2(a.x * b.x - a.y * b.y, a.x * b.y + a.y * b.x);
}

// packed f32x2 helpers (sm_103a)
__device__ __forceinline__ unsigned long long pack2(float lo, float hi) {
    unsigned long long r;
    asm("mov.b64 %0, {%1, %2};" : "=l"(r) : "f"(lo), "f"(hi));
    return r;
}
__device__ __forceinline__ void unpack2(unsigned long long v, float& lo, float& hi) {
    asm("mov.b64 {%0, %1}, %2;" : "=f"(lo), "=f"(hi) : "l"(v));
}
__device__ __forceinline__ unsigned long long fma2(unsigned long long a,
                                                   unsigned long long b,
                                                   unsigned long long c) {
    unsigned long long d;
    asm("fma.rn.f32x2 %0, %1, %2, %3;" : "=l"(d) : "l"(a), "l"(b), "l"(c));
    return d;
}

// ---------------------------------------------------------------------------
// Kernel 1 (fused): per token:
//   enc = normalize(x @ W^T + b)
//   u = Ga * enc, v = Gb * enc          (32x32 complex * real vec)
//   P_k[r] = sum_{m:m&1==pa} G2a[r][m^fa] * u[m ^ (m>>1)]
//   Q_k[r] = sum_{m:m&1==pb} G2b[r][m]  * v[(m ^ (m>>1)) ^ xb]
// where Ga = kron(RY0*RX0) over wires 0..4, Gb over 5..9, G2a/G2b = kron(RY1),
// sigma_inv(m) = m ^ (m>>1) is the CNOT prefix-chain inverse, and
// (pa,fa,pb,xb) encode the rank-4 split over cross CNOTs (4,5),(9,0):
//   pa = k>>1, fa = (k&1)<<4, pb = k&1, xb = (k>>1)<<4.
// Each block rebuilds Ga/Gb/G2a/G2b locally from the thetas (~trivial work).
// grid = 128 (one block per token), block = 128 threads.
// ---------------------------------------------------------------------------
__global__ void __launch_bounds__(128)
enc_pq_kernel(const float* __restrict__ x,
              const float* __restrict__ W,
              const float* __restrict__ bias,
              const float* __restrict__ th_rx0,
              const float* __restrict__ th_ry0,
              const float* __restrict__ th_ry1) {
    __shared__ float2 M1w[10][2][2];  // layer-1 combined RY*RX per wire
    __shared__ float  M2w[10][2][2];  // layer-2 RY per wire (real)
    __shared__ float2 Ga[32][32], Gb[32][32];
    __shared__ float  G2a[32][32], G2b[32][32];
    __shared__ float  partial[4][32];
    __shared__ float  e[32];
    __shared__ float2 us[32], vs[32];

    int tok = blockIdx.x;
    int tid = threadIdx.x;  // 128

    if (tid < 10) {
        float crx = cosf(th_rx0[tid] * 0.5f), srx = sinf(th_rx0[tid] * 0.5f);
        float cry = cosf(th_ry0[tid] * 0.5f), sry = sinf(th_ry0[tid] * 0.5f);
        // M = RY * RX
        M1w[tid][0][0] = make_float2( cry * crx,  sry * srx);
        M1w[tid][0][1] = make_float2(-sry * crx, -cry * srx);
        M1w[tid][1][0] = make_float2( sry * crx, -cry * srx);
        M1w[tid][1][1] = make_float2( cry * crx, -sry * srx);
        float c1 = cosf(th_ry1[tid] * 0.5f), s1 = sinf(th_ry1[tid] * 0.5f);
        M2w[tid][0][0] =  c1; M2w[tid][0][1] = -s1;
        M2w[tid][1][0] =  s1; M2w[tid][1][1] =  c1;
    }
    __syncthreads();

    // Build the four 32x32 Kronecker factors (8 cells per thread)
    for (int cell = tid; cell < 1024; cell += 128) {
        int r = cell >> 5, c = cell & 31;
        float2 ga = make_float2(1.f, 0.f), gb = make_float2(1.f, 0.f);
        float g2a = 1.f, g2b = 1.f;
#pragma unroll
        for (int j = 0; j < 5; j++) {
            int rb = (r >> (4 - j)) & 1;
            int cb = (c >> (4 - j)) & 1;
            ga  = cmul(ga, M1w[j][rb][cb]);
            gb  = cmul(gb, M1w[5 + j][rb][cb]);
            g2a *= M2w[j][rb][cb];
            g2b *= M2w[5 + j][rb][cb];
        }
        Ga[r][c] = ga; Gb[r][c] = gb; G2a[r][c] = g2a; G2b[r][c] = g2b;
    }

    // GEMV partials: thread (p,k) sums 128 c-elements of row k (float4 loads)
    {
        int k = tid & 31, p = tid >> 5;
        const float4* wr4 = (const float4*)(W + (size_t)k * C + p * 128);
        const float4* xc4 = (const float4*)(x + (size_t)tok * C + p * 128);
        float s = 0.f;
#pragma unroll
        for (int cc = 0; cc < 32; cc++) {
            float4 wv = wr4[cc];
            float4 xv = xc4[cc];
            s += wv.x * xv.x + wv.y * xv.y + wv.z * xv.z + wv.w * xv.w;
        }
        partial[p][k] = s;
    }
    __syncthreads();

    if (tid < 32) {
        float v = partial[0][tid] + partial[1][tid] + partial[2][tid] +
                  partial[3][tid] + bias[tid];
        float sq = v * v;
#pragma unroll
        for (int o = 16; o; o >>= 1) sq += __shfl_xor_sync(0xffffffffu, sq, o);
        e[tid] = v * rsqrtf(sq);
    }
    __syncthreads();

    // u = Ga * e, v = Gb * e  (threads 0..63)
    if (tid < 64) {
        int r = tid & 31, side = tid >> 5;
        float re = 0.f, im = 0.f;
#pragma unroll
        for (int c = 0; c < 32; c++) {
            float ev = e[c];
            float2 m = side ? Gb[r][c] : Ga[r][c];
            re += m.x * ev; im += m.y * ev;
        }
        if (side) vs[r] = make_float2(re, im);
        else      us[r] = make_float2(re, im);
    }
    __syncthreads();

    // P/Q: 256 complex outputs, 2 per thread
#pragma unroll
    for (int pass = 0; pass < 2; pass++) {
        int o = tid + pass * 128;
        int which = o >> 7;             // 0 -> P, 1 -> Q
        int k4 = (o >> 5) & 3;
        int rr = o & 31;
        float re = 0.f, im = 0.f;
        if (which == 0) {
            int pa = k4 >> 1, fa = (k4 & 1) << 4;
#pragma unroll
            for (int mm = 0; mm < 16; mm++) {
                int m = (mm << 1) | pa;
                float2 uu = us[m ^ (m >> 1)];
                float g = G2a[rr][m ^ fa];
                re += g * uu.x; im += g * uu.y;
            }
            d_P[tok][k4][rr] = make_float2(re, im);
        } else {
            int pb = k4 & 1, xb = (k4 >> 1) << 4;
#pragma unroll
            for (int mm = 0; mm < 16; mm++) {
                int m = (mm << 1) | pb;
                float2 vv = vs[(m ^ (m >> 1)) ^ xb];
                float g = G2b[rr][m];
                re += g * vv.x; im += g * vv.y;
            }
            d_Q[tok][k4][rr] = make_float2(re, im);
        }
    }
}

// ---------------------------------------------------------------------------
// Kernel 2a: rank-4 expansion, interleaved complex64 output (re,im pairs).
// out[b, i*T+j, a*32 + bi] = sum_k P_k(b,i)[a] * Q_k(b,j)[bi]
// grid = 4096 blocks, block = 512; each thread writes 2 complex = 1 float4.
// Complex MACs via packed fma.rn.f32x2: acc=(re,im);
//   acc += (P.x,P.x)*(Q.x,Q.y) + (-P.y,P.y)*(Q.y,Q.x)
// ---------------------------------------------------------------------------
__global__ void __launch_bounds__(512)
expand_cplx_kernel(float4* __restrict__ out, long long nf4_limit) {
    int blk = blockIdx.x;          // b*1024 + i*32 + j
    int b = blk >> 10;
    int i = (blk >> 5) & 31;
    int j = blk & 31;

    __shared__ float2 Ps[4][32];
    __shared__ float2 Qs[4][32];

    int tid = threadIdx.x;  // 512
    if (tid < 128) {
        Ps[tid >> 5][tid & 31] = d_P[b * T + i][tid >> 5][tid & 31];
    } else if (tid < 256) {
        int t = tid - 128;
        Qs[t >> 5][t & 31] = d_Q[b * T + j][t >> 5][t & 31];
    }
    __syncthreads();

    int e0 = tid * 2;
    int a  = e0 >> 5;
    int b0 = e0 & 31;

    unsigned long long acc0 = pack2(0.f, 0.f);
    unsigned long long acc1 = pack2(0.f, 0.f);
#pragma unroll
    for (int k = 0; k < 4; k++) {
        float2 P  = Ps[k][a];
        float2 Q0 = Qs[k][b0];
        float2 Q1 = Qs[k][b0 + 1];
        unsigned long long pxx = pack2(P.x, P.x);
        unsigned long long pyn = pack2(-P.y, P.y);
        acc0 = fma2(pxx, pack2(Q0.x, Q0.y), acc0);
        acc0 = fma2(pyn, pack2(Q0.y, Q0.x), acc0);
        acc1 = fma2(pxx, pack2(Q1.x, Q1.y), acc1);
        acc1 = fma2(pyn, pack2(Q1.y, Q1.x), acc1);
    }
    float re0, im0, re1, im1;
    unpack2(acc0, re0, im0);
    unpack2(acc1, re1, im1);

    long long idx = (long long)blk * 512 + tid;
    if (idx < nf4_limit)
        out[idx] = make_float4(re0, im0, re1, im1);
}

// ---------------------------------------------------------------------------
// Kernel 2b: rank-4 expansion, REAL-part-only float32 output (4M floats).
// (fallback branch; not the live path on this dataset)
// ---------------------------------------------------------------------------
__global__ void __launch_bounds__(512)
expand_real_kernel(float2* __restrict__ out) {
    int blk = blockIdx.x;
    int b = blk >> 10;
    int i = (blk >> 5) & 31;
    int j = blk & 31;

    __shared__ float2 Ps[4][32];
    __shared__ float2 Qs[4][32];

    int tid = threadIdx.x;  // 512
    if (tid < 128) {
        Ps[tid >> 5][tid & 31] = d_P[b * T + i][tid >> 5][tid & 31];
    } else if (tid < 256) {
        int t = tid - 128;
        Qs[t >> 5][t & 31] = d_Q[b * T + j][t >> 5][t & 31];
    }
    __syncthreads();

    int e0 = tid * 2;
    int a  = e0 >> 5;
    int b0 = e0 & 31;

    float re0 = 0.f, re1 = 0.f;
#pragma unroll
    for (int k = 0; k < 4; k++) {
        float2 P  = Ps[k][a];
        float2 Q0 = Qs[k][b0];
        float2 Q1 = Qs[k][b0 + 1];
        re0 += P.x * Q0.x - P.y * Q0.y;
        re1 += P.x * Q1.x - P.y * Q1.y;
    }
    out[(long long)blk * 512 + tid] = make_float2(re0, re1);
}

// ---------------------------------------------------------------------------
extern "C" void kernel_launch(void* const* d_in, const int* in_sizes, int n_in,
                              void* d_out, int out_size) {
    // Resolve inputs by element count (order-independent):
    //   x: 65536 (B*T*C), W_tok: 16384 (ENC*C), b_tok: 32 (ENC),
    //   thetas: three size-10 arrays, relative order rx0, ry0, ry1.
    const float* x = nullptr;
    const float* W = nullptr;
    const float* bvec = nullptr;
    const float* th[3] = {nullptr, nullptr, nullptr};
    int nth = 0;
    for (int i = 0; i < n_in; i++) {
        int sz = in_sizes[i];
        const float* p = (const float*)d_in[i];
        if (sz == BATCH * T * C)      x = p;
        else if (sz == ENC * C)       W = p;
        else if (sz == ENC)           bvec = p;
        else if (sz == 10 && nth < 3) th[nth++] = p;
    }
    if (!x || !W || !bvec || nth != 3) return;

    enc_pq_kernel<<<NTOK, 128>>>(x, W, bvec, th[0], th[1], th[2]);

    if (out_size == 4194304) {
        // float32 output, 4M elements (16MB): real parts only.
        expand_real_kernel<<<BATCH * T * T, 512>>>((float2*)d_out);
    } else {
        // Interleaved (re,im) float pairs: 8M floats = 2M float4 (32MB).
        long long nfloats = (long long)out_size;
        if (nfloats > 8388608LL) nfloats = 8388608LL;
        long long nf4 = nfloats / 4;
        if (nf4 > 2097152LL) nf4 = 2097152LL;
        expand_cplx_kernel<<<BATCH * T * T, 512>>>((float4*)d_out, nf4);
    }
}

// round 8
// speedup vs baseline: 1.9421x; 1.2262x over previous
#include <cuda_runtime.h>

// Problem constants
#define BATCH 4
#define T 32
#define NTOK (BATCH * T)      // 128
#define C 512
#define ENC 32
#define DIM 1024

// Scratch (no allocations allowed): device globals
__device__ float2 d_P[NTOK][4][32];
__device__ float2 d_Q[NTOK][4][32];

__device__ __forceinline__ float2 cmul(float2 a, float2 b) {
    return make_float2(a.x * b.x - a.y * b.y, a.x * b.y + a.y * b.x);
}

// packed f32x2 helpers (sm_103a)
__device__ __forceinline__ unsigned long long pack2(float lo, float hi) {
    unsigned long long r;
    asm("mov.b64 %0, {%1, %2};" : "=l"(r) : "f"(lo), "f"(hi));
    return r;
}
__device__ __forceinline__ void unpack2(unsigned long long v, float& lo, float& hi) {
    asm("mov.b64 {%0, %1}, %2;" : "=f"(lo), "=f"(hi) : "l"(v));
}
__device__ __forceinline__ unsigned long long fma2(unsigned long long a,
                                                   unsigned long long b,
                                                   unsigned long long c) {
    unsigned long long d;
    asm("fma.rn.f32x2 %0, %1, %2, %3;" : "=l"(d) : "l"(a), "l"(b), "l"(c));
    return d;
}

// ---------------------------------------------------------------------------
// Kernel 1 (fused): per token:
//   enc = normalize(x @ W^T + b)
//   u = Ga * enc, v = Gb * enc          (32x32 complex * real vec)
//   P_k[r] = sum_{m:m&1==pa} G2a[r][m^fa] * u[m ^ (m>>1)]
//   Q_k[r] = sum_{m:m&1==pb} G2b[r][m]  * v[(m ^ (m>>1)) ^ xb]
// where Ga = kron(RY0*RX0) over wires 0..4, Gb over 5..9, G2a/G2b = kron(RY1),
// sigma_inv(m) = m ^ (m>>1) is the CNOT prefix-chain inverse, and
// (pa,fa,pb,xb) encode the rank-4 split over cross CNOTs (4,5),(9,0):
//   pa = k>>1, fa = (k&1)<<4, pb = k&1, xb = (k>>1)<<4.
// grid = 128 (one block per token), block = 128 threads.
// ---------------------------------------------------------------------------
__global__ void __launch_bounds__(128)
enc_pq_kernel(const float* __restrict__ x,
              const float* __restrict__ W,
              const float* __restrict__ bias,
              const float* __restrict__ th_rx0,
              const float* __restrict__ th_ry0,
              const float* __restrict__ th_ry1) {
    __shared__ float2 M1w[10][2][2];  // layer-1 combined RY*RX per wire
    __shared__ float  M2w[10][2][2];  // layer-2 RY per wire (real)
    __shared__ float2 Ga[32][32], Gb[32][32];
    __shared__ float  G2a[32][32], G2b[32][32];
    __shared__ float  partial[4][32];
    __shared__ float  e[32];
    __shared__ float2 us[32], vs[32];

    int tok = blockIdx.x;
    int tid = threadIdx.x;  // 128

    if (tid < 10) {
        float crx = cosf(th_rx0[tid] * 0.5f), srx = sinf(th_rx0[tid] * 0.5f);
        float cry = cosf(th_ry0[tid] * 0.5f), sry = sinf(th_ry0[tid] * 0.5f);
        // M = RY * RX
        M1w[tid][0][0] = make_float2( cry * crx,  sry * srx);
        M1w[tid][0][1] = make_float2(-sry * crx, -cry * srx);
        M1w[tid][1][0] = make_float2( sry * crx, -cry * srx);
        M1w[tid][1][1] = make_float2( cry * crx, -sry * srx);
        float c1 = cosf(th_ry1[tid] * 0.5f), s1 = sinf(th_ry1[tid] * 0.5f);
        M2w[tid][0][0] =  c1; M2w[tid][0][1] = -s1;
        M2w[tid][1][0] =  s1; M2w[tid][1][1] =  c1;
    }
    __syncthreads();

    // Build the four 32x32 Kronecker factors (8 cells per thread)
    for (int cell = tid; cell < 1024; cell += 128) {
        int r = cell >> 5, c = cell & 31;
        float2 ga = make_float2(1.f, 0.f), gb = make_float2(1.f, 0.f);
        float g2a = 1.f, g2b = 1.f;
#pragma unroll
        for (int j = 0; j < 5; j++) {
            int rb = (r >> (4 - j)) & 1;
            int cb = (c >> (4 - j)) & 1;
            ga  = cmul(ga, M1w[j][rb][cb]);
            gb  = cmul(gb, M1w[5 + j][rb][cb]);
            g2a *= M2w[j][rb][cb];
            g2b *= M2w[5 + j][rb][cb];
        }
        Ga[r][c] = ga; Gb[r][c] = gb; G2a[r][c] = g2a; G2b[r][c] = g2b;
    }

    // GEMV partials: thread (p,k) sums 128 c-elements of row k (float4 loads)
    {
        int k = tid & 31, p = tid >> 5;
        const float4* wr4 = (const float4*)(W + (size_t)k * C + p * 128);
        const float4* xc4 = (const float4*)(x + (size_t)tok * C + p * 128);
        float s = 0.f;
#pragma unroll
        for (int cc = 0; cc < 32; cc++) {
            float4 wv = wr4[cc];
            float4 xv = xc4[cc];
            s += wv.x * xv.x + wv.y * xv.y + wv.z * xv.z + wv.w * xv.w;
        }
        partial[p][k] = s;
    }
    __syncthreads();

    if (tid < 32) {
        float v = partial[0][tid] + partial[1][tid] + partial[2][tid] +
                  partial[3][tid] + bias[tid];
        float sq = v * v;
#pragma unroll
        for (int o = 16; o; o >>= 1) sq += __shfl_xor_sync(0xffffffffu, sq, o);
        e[tid] = v * rsqrtf(sq);
    }
    __syncthreads();

    // u = Ga * e, v = Gb * e  (threads 0..63)
    if (tid < 64) {
        int r = tid & 31, side = tid >> 5;
        float re = 0.f, im = 0.f;
#pragma unroll
        for (int c = 0; c < 32; c++) {
            float ev = e[c];
            float2 m = side ? Gb[r][c] : Ga[r][c];
            re += m.x * ev; im += m.y * ev;
        }
        if (side) vs[r] = make_float2(re, im);
        else      us[r] = make_float2(re, im);
    }
    __syncthreads();

    // P/Q: 256 complex outputs, 2 per thread
#pragma unroll
    for (int pass = 0; pass < 2; pass++) {
        int o = tid + pass * 128;
        int which = o >> 7;             // 0 -> P, 1 -> Q
        int k4 = (o >> 5) & 3;
        int rr = o & 31;
        float re = 0.f, im = 0.f;
        if (which == 0) {
            int pa = k4 >> 1, fa = (k4 & 1) << 4;
#pragma unroll
            for (int mm = 0; mm < 16; mm++) {
                int m = (mm << 1) | pa;
                float2 uu = us[m ^ (m >> 1)];
                float g = G2a[rr][m ^ fa];
                re += g * uu.x; im += g * uu.y;
            }
            d_P[tok][k4][rr] = make_float2(re, im);
        } else {
            int pb = k4 & 1, xb = (k4 >> 1) << 4;
#pragma unroll
            for (int mm = 0; mm < 16; mm++) {
                int m = (mm << 1) | pb;
                float2 vv = vs[(m ^ (m >> 1)) ^ xb];
                float g = G2b[rr][m];
                re += g * vv.x; im += g * vv.y;
            }
            d_Q[tok][k4][rr] = make_float2(re, im);
        }
    }
}

// ---------------------------------------------------------------------------
// Kernel 2: rank-4 expansion, REAL parts, restructured for arithmetic density.
// One block per (b,i); block stages all Q of batch b in SoA smem once, then
// loops over j. Thread owns a 4a x 4b0 patch: P packed in regs outside the
// j-loop, per-j only 8 LDS.128 (Q) + 64 fma.rn.f32x2 + 4 STG.128.
//   out[(b*1024 + i*32 + j)*1024 + a*32 + b0] =
//       sum_k P_k(b,i)[a].x*Q_k(b,j)[b0].x - P_k[a].y*Q_k[b0].y
// grid = 128, block = 256 (4 j-lanes x 64 patch-threads).
// ---------------------------------------------------------------------------
__global__ void __launch_bounds__(256)
expand_real2_kernel(float* __restrict__ out) {
    int blk = blockIdx.x;       // b*32 + i
    int b = blk >> 5, i = blk & 31;

    __shared__ float  Qx[32][4][32];   // [j][k][b0]
    __shared__ float  Qy[32][4][32];
    __shared__ float2 Psm[4][32];      // [k][a]

    int t = threadIdx.x;  // 256

    // Stage all Q of batch b: 4096 float2, flat index n = j*128 + k*32 + b0
    {
        const float2* qsrc = &d_Q[b * T][0][0];
        float* qx = &Qx[0][0][0];
        float* qy = &Qy[0][0][0];
#pragma unroll
        for (int n = 0; n < 16; n++) {
            int idx = t + n * 256;
            float2 v = qsrc[idx];
            qx[idx] = v.x;
            qy[idx] = v.y;
        }
    }
    if (t < 128) {
        Psm[t >> 5][t & 31] = d_P[b * T + i][t >> 5][t & 31];
    }
    __syncthreads();

    int jj = t >> 6;            // 0..3: which j within each group of 4
    int t4 = t & 63;
    int a_base = (t4 >> 3) << 2;   // 0,4,...,28
    int b0 = (t4 & 7) << 2;        // 0,4,...,28

    // Pack P into registers: (P.x,P.x) and (-P.y,-P.y) per (da,k)
    unsigned long long pxx[4][4], pyn[4][4];
#pragma unroll
    for (int da = 0; da < 4; da++)
#pragma unroll
        for (int k = 0; k < 4; k++) {
            float2 P = Psm[k][a_base + da];
            pxx[da][k] = pack2(P.x, P.x);
            pyn[da][k] = pack2(-P.y, -P.y);
        }

    float* obase = out + (((size_t)b * 1024 + (size_t)i * 32) << 10);

#pragma unroll
    for (int jo = 0; jo < 8; jo++) {
        int j = (jo << 2) | jj;
        // Q pairs for this j: per k one LDS.128 from Qx and one from Qy
        ulonglong2 qxv[4], qyv[4];
#pragma unroll
        for (int k = 0; k < 4; k++) {
            qxv[k] = *(const ulonglong2*)&Qx[j][k][b0];
            qyv[k] = *(const ulonglong2*)&Qy[j][k][b0];
        }
        float* oj = obase + ((size_t)j << 10);
#pragma unroll
        for (int da = 0; da < 4; da++) {
            unsigned long long accL = 0ull, accH = 0ull;  // bits(0)=0.0f pairs
#pragma unroll
            for (int k = 0; k < 4; k++) {
                accL = fma2(pxx[da][k], qxv[k].x, accL);
                accL = fma2(pyn[da][k], qyv[k].x, accL);
                accH = fma2(pxx[da][k], qxv[k].y, accH);
                accH = fma2(pyn[da][k], qyv[k].y, accH);
            }
            float r0, r1, r2, r3;
            unpack2(accL, r0, r1);
            unpack2(accH, r2, r3);
            *(float4*)&oj[(a_base + da) * 32 + b0] = make_float4(r0, r1, r2, r3);
        }
    }
}

// ---------------------------------------------------------------------------
// Kernel 2b: interleaved complex64 fallback (not the live path; kept for
// robustness against out_size layout changes).
// ---------------------------------------------------------------------------
__global__ void __launch_bounds__(512)
expand_cplx_kernel(float4* __restrict__ out, long long nf4_limit) {
    int blk = blockIdx.x;          // b*1024 + i*32 + j
    int b = blk >> 10;
    int i = (blk >> 5) & 31;
    int j = blk & 31;

    __shared__ float2 Ps[4][32];
    __shared__ float2 Qs[4][32];

    int tid = threadIdx.x;  // 512
    if (tid < 128) {
        Ps[tid >> 5][tid & 31] = d_P[b * T + i][tid >> 5][tid & 31];
    } else if (tid < 256) {
        int t = tid - 128;
        Qs[t >> 5][t & 31] = d_Q[b * T + j][t >> 5][t & 31];
    }
    __syncthreads();

    int e0 = tid * 2;
    int a  = e0 >> 5;
    int b0 = e0 & 31;

    unsigned long long acc0 = 0ull, acc1 = 0ull;
#pragma unroll
    for (int k = 0; k < 4; k++) {
        float2 P  = Ps[k][a];
        float2 Q0 = Qs[k][b0];
        float2 Q1 = Qs[k][b0 + 1];
        unsigned long long pxx = pack2(P.x, P.x);
        unsigned long long pyn = pack2(-P.y, P.y);
        acc0 = fma2(pxx, pack2(Q0.x, Q0.y), acc0);
        acc0 = fma2(pyn, pack2(Q0.y, Q0.x), acc0);
        acc1 = fma2(pxx, pack2(Q1.x, Q1.y), acc1);
        acc1 = fma2(pyn, pack2(Q1.y, Q1.x), acc1);
    }
    float re0, im0, re1, im1;
    unpack2(acc0, re0, im0);
    unpack2(acc1, re1, im1);

    long long idx = (long long)blk * 512 + tid;
    if (idx < nf4_limit)
        out[idx] = make_float4(re0, im0, re1, im1);
}

// ---------------------------------------------------------------------------
extern "C" void kernel_launch(void* const* d_in, const int* in_sizes, int n_in,
                              void* d_out, int out_size) {
    // Resolve inputs by element count (order-independent):
    //   x: 65536 (B*T*C), W_tok: 16384 (ENC*C), b_tok: 32 (ENC),
    //   thetas: three size-10 arrays, relative order rx0, ry0, ry1.
    const float* x = nullptr;
    const float* W = nullptr;
    const float* bvec = nullptr;
    const float* th[3] = {nullptr, nullptr, nullptr};
    int nth = 0;
    for (int i = 0; i < n_in; i++) {
        int sz = in_sizes[i];
        const float* p = (const float*)d_in[i];
        if (sz == BATCH * T * C)      x = p;
        else if (sz == ENC * C)       W = p;
        else if (sz == ENC)           bvec = p;
        else if (sz == 10 && nth < 3) th[nth++] = p;
    }
    if (!x || !W || !bvec || nth != 3) return;

    enc_pq_kernel<<<NTOK, 128>>>(x, W, bvec, th[0], th[1], th[2]);

    if (out_size == 4194304) {
        // Live path: float32 output, 4M elements (16MB): real parts only.
        expand_real2_kernel<<<NTOK, 256>>>((float*)d_out);
    } else {
        // Interleaved (re,im) float pairs: 8M floats = 2M float4 (32MB).
        long long nfloats = (long long)out_size;
        if (nfloats > 8388608LL) nfloats = 8388608LL;
        long long nf4 = nfloats / 4;
        if (nf4 > 2097152LL) nf4 = 2097152LL;
        expand_cplx_kernel<<<BATCH * T * T, 512>>>((float4*)d_out, nf4);
    }
}